// round 1
// baseline (speedup 1.0000x reference)
#include <cuda_runtime.h>

// Spline upsample: not-a-knot cubic, uniform grid, B x W fp32 -> B x (W*ups).
// Tridiagonal [1,4,1] solve replaced by exact Green's-function FIR:
//   T_n^{-1}[i,j] = A*( lam^|i-j| - lam^{i+j+2} - lam^{(n-i)+(n-j)} ) + O(lam^n)
// with lam = sqrt(3)-2, A = 1/(2*sqrt(3)). |lam|^12 ~ 1.3e-7 -> 12-tap kernel.

#define W_DIM 8192
#define NTHR  512
#define KTAP  12
#define PADL  16

#define LAM  (-0.26794919243112270647f)   // sqrt(3) - 2
#define ACOEF (0.28867513459481288225f)   // 1 / (2*sqrt(3))

__global__ __launch_bounds__(NTHR, 2)
void spline_kernel(const float* __restrict__ x, float* __restrict__ out,
                   int nout, float step) {
    extern __shared__ float sm[];
    const int n = W_DIM - 4;                     // 8188
    float* sy    = sm;                           // [0, W)
    float* sbRaw = sm + W_DIM;                   // n + 32 (16-float pad each side)
    float* sb    = sbRaw + PADL;
    float* sM    = sm + W_DIM + n + 2 * PADL;    // W floats
    float* sS    = sM + W_DIM;                   // 2 floats: S_L, S_R
    float* sPW   = sS + 2;                       // 32 floats: lam^(t+1)

    const int tid = threadIdx.x;
    const int row = blockIdx.x;
    const float* xr = x + (size_t)row * W_DIM;
    float* outr = out + (size_t)row * nout;

    // ---- Phase A: load row into smem (vectorized) ----
    {
        const float4* x4 = (const float4*)xr;
        float4* sy4 = (float4*)sy;
        #pragma unroll
        for (int v = tid; v < W_DIM / 4; v += NTHR) sy4[v] = x4[v];
    }
    __syncthreads();

    // ---- Phase B: rhs b[j] = 6*(y[j+3]-2y[j+2]+y[j+1]), j=0..n-1, with
    //      b[0]   -= M1  = y[2]-2y[1]+y[0]
    //      b[n-1] -= Mn2 = y[W-1]-2y[W-2]+y[W-3]
    for (int j = tid; j < n; j += NTHR) {
        float b = 6.0f * (sy[j + 3] - 2.0f * sy[j + 2] + sy[j + 1]);
        if (j == 0)     b -= (sy[2] - 2.0f * sy[1] + sy[0]);
        if (j == n - 1) b -= (sy[W_DIM - 1] - 2.0f * sy[W_DIM - 2] + sy[W_DIM - 3]);
        sb[j] = b;
    }
    // zero the pad wings
    if (tid < PADL)              sb[tid - PADL] = 0.0f;
    else if (tid < 2 * PADL)     sb[n + tid - PADL] = 0.0f;
    // power table: sPW[t] = lam^(t+1), t = 0..31
    if (tid < 32) {
        float p = 1.0f;
        for (int s = 0; s <= tid; ++s) p *= LAM;
        sPW[tid] = p;
    }
    __syncthreads();

    // ---- Phase C: boundary image sums (truncated at lam^24 ~ 2e-14) ----
    if (tid == 0) {
        float s = 0.0f;
        for (int m = 0; m < 24; ++m) s += sPW[m] * sb[m];
        sS[0] = s;                               // S_L = sum lam^{j+1} b_j
    }
    if (tid == 32) {
        float s = 0.0f;
        for (int m = 0; m < 24; ++m) s += sPW[m] * sb[n - 1 - m];
        sS[1] = s;                               // S_R = sum lam^{m+1} b_{n-1-m}
    }
    __syncthreads();

    // ---- Phase D: FIR solve  Mi[j] = A*( sum_k lam^|k| b[j+k] - corr ) ----
    {
        const float S_L = sS[0];
        const float S_R = sS[1];
        const int nchunk = n / 4;                // 2047 (n divisible by 4)
        for (int c = tid; c < nchunk; c += NTHR) {
            const int j0 = 4 * c;
            float win[2 * KTAP + 4];
            const float4* wsrc = (const float4*)(sb + j0 - KTAP);
            #pragma unroll
            for (int v = 0; v < (2 * KTAP + 4) / 4; ++v)
                ((float4*)win)[v] = wsrc[v];
            #pragma unroll
            for (int m = 0; m < 4; ++m) {
                float acc = win[KTAP + m];
                float lp = 1.0f;
                #pragma unroll
                for (int k = 1; k <= KTAP; ++k) {
                    lp *= LAM;                   // constant-folded per k
                    acc = fmaf(lp, win[KTAP + m - k] + win[KTAP + m + k], acc);
                }
                const int jj = j0 + m;
                if (jj < 32)         acc -= sPW[jj] * S_L;
                const int rr = n - 1 - jj;
                if (rr < 32)         acc -= sPW[rr] * S_R;
                sM[2 + jj] = ACOEF * acc;
            }
        }
    }
    __syncthreads();

    // ---- Phase E: boundary second derivatives ----
    if (tid == 0) {
        const float M1  = sy[2] - 2.0f * sy[1] + sy[0];
        const float Mn2 = sy[W_DIM - 1] - 2.0f * sy[W_DIM - 2] + sy[W_DIM - 3];
        sM[1] = M1;
        sM[W_DIM - 2] = Mn2;
        sM[0] = 2.0f * M1 - sM[2];
        sM[W_DIM - 1] = 2.0f * Mn2 - sM[W_DIM - 3];
    }
    __syncthreads();

    // ---- Phase F: evaluate spline at nout points, float4 stores ----
    {
        float4* out4 = (float4*)outr;
        const int nq4 = nout / 4;
        for (int c = tid; c < nq4; c += NTHR) {
            const int q0 = 4 * c;
            float4 r;
            #pragma unroll
            for (int m = 0; m < 4; ++m) {
                const float xq = (float)(q0 + m) * step;
                int i = (int)xq;
                if (i > W_DIM - 2) i = W_DIM - 2;
                const float t  = xq - (float)i;
                const float y0 = sy[i],  y1 = sy[i + 1];
                const float m0 = sM[i],  m1 = sM[i + 1];
                const float bb = (y1 - y0) - (2.0f * m0 + m1) * (1.0f / 6.0f);
                ((float*)&r)[m] =
                    y0 + t * (bb + t * (0.5f * m0 + t * (m1 - m0) * (1.0f / 6.0f)));
            }
            out4[c] = r;
        }
    }
}

extern "C" void kernel_launch(void* const* d_in, const int* in_sizes, int n_in,
                              void* d_out, int out_size) {
    const float* x = (const float*)d_in[0];
    float* out = (float*)d_out;

    const int total_in = in_sizes[0];
    const int B = total_in / W_DIM;              // 512
    const int nout = out_size / B;               // W * upsample_rate = 32768
    const float step = (float)((double)(W_DIM - 1) / (double)(nout - 1));

    const int n = W_DIM - 4;
    const size_t smem_bytes =
        (size_t)(W_DIM + (n + 2 * PADL) + W_DIM + 2 + 32) * sizeof(float); // ~98.5 KB

    static int attr_set = 0;
    // cudaFuncSetAttribute is idempotent and not a stream op; safe under capture.
    cudaFuncSetAttribute(spline_kernel,
                         cudaFuncAttributeMaxDynamicSharedMemorySize,
                         (int)smem_bytes);
    (void)attr_set;

    spline_kernel<<<B, NTHR, smem_bytes>>>(x, out, nout, step);
}